// round 17
// baseline (speedup 1.0000x reference)
#include <cuda_runtime.h>
#include <cuda_bf16.h>
#include <cuda_fp16.h>
#include <mma.h>
#include <cstdint>
#include <math.h>

using namespace nvcuda;

#define H       1024
#define DIN     512
#define T_STEPS 512
#define BATCH   32
#define DT_C    0.1f

#define GRID_R  128
#define BLOCK_R 768
#define HB      8      // H / GRID_R
#define GB      16     // batches per group

typedef unsigned long long u64;

// ---------------- f32x2 packed math (Blackwell) ----------------
__device__ __forceinline__ u64 fma2(u64 a, u64 b, u64 c) {
    u64 d;
    asm("fma.rn.f32x2 %0, %1, %2, %3;" : "=l"(d) : "l"(a), "l"(b), "l"(c));
    return d;
}
__device__ __forceinline__ u64 add2(u64 a, u64 b) {
    u64 d;
    asm("add.rn.f32x2 %0, %1, %2;" : "=l"(d) : "l"(a), "l"(b));
    return d;
}
__device__ __forceinline__ u64 dup2u(unsigned a) {
    u64 d;
    asm("mov.b64 %0, {%1, %1};" : "=l"(d) : "r"(a));
    return d;
}
__device__ __forceinline__ unsigned bf_lo(unsigned x) {
    unsigned r;
    asm("prmt.b32 %0, %1, %2, 0x1044;" : "=r"(r) : "r"(x), "r"(0u));
    return r;
}
__device__ __forceinline__ unsigned bf_hi(unsigned x) {
    unsigned r;
    asm("prmt.b32 %0, %1, %2, 0x3244;" : "=r"(r) : "r"(x), "r"(0u));
    return r;
}
__device__ __forceinline__ float tanh_fast(float x) {
    float e = __expf(2.0f * x);
    return 1.0f - __fdividef(2.0f, e + 1.0f);
}
__device__ __forceinline__ float sigmoid_fast(float x) {
    return __fdividef(1.0f, 1.0f + __expf(-x));
}

// ---------------- device scratch (static, allocation-free) ----------------
__device__ float g_Wr[H * H];
__device__ float g_Wi[H * H];
__device__ float g_Ux[T_STEPS * BATCH * H];
__device__ __half g_ZRh[T_STEPS * BATCH * H];         // fp16 zr history (out-GEMM A)
__device__ __half g_xh[T_STEPS * BATCH * DIN];
__device__ __half g_Uwh[H * DIN];
__device__ __half g_owh[H * H];
__device__ __nv_bfloat16 g_act[2 * 2 * 3 * H * GB];   // [buf][grp][mat][k][16b], bf16
__device__ unsigned g_cnt2[2];
__device__ unsigned g_gen2[2];

// ---------------- split grid barriers (two phase-shifted barriers) ----------------
__device__ __forceinline__ void gbar_arrive(int id) {
    // caller must have __syncthreads()'d after its stores
    if (threadIdx.x == 0) {
        __threadfence();
        unsigned v = atomicAdd(&g_cnt2[id], 1u);
        if (v == GRID_R - 1) {
            g_cnt2[id] = 0u;
            __threadfence();
            atomicAdd(&g_gen2[id], 1u);
        }
    }
}
__device__ __forceinline__ void gbar_wait(int id, int target) {
    if (threadIdx.x == 0) {
        while ((int)(*(volatile unsigned*)&g_gen2[id]) < target) { }
        __threadfence();   // CCTL.IVALL: invalidate L1 so fresh acts are read
    }
    __syncthreads();
}

// ---------------- prep kernels ----------------
__global__ void prep_kernel(const float* __restrict__ Wr_w, const float* __restrict__ mask_r,
                            const float* __restrict__ Wi_w, const float* __restrict__ mask_i) {
    int i = blockIdx.x * blockDim.x + threadIdx.x;
    if (i < H * H) {
        g_Wr[i] = Wr_w[i] * (1.0f / (1.0f + expf(-mask_r[i])));
        g_Wi[i] = Wi_w[i] * (1.0f / (1.0f + expf(-mask_i[i])));
    }
}

__global__ void init_kernel() {
    int i = blockIdx.x * blockDim.x + threadIdx.x;
    if (i < 2 * 2 * 3 * H * GB) g_act[i] = __float2bfloat16(0.0f);
    if (i < 2) { g_gen2[i] = 0u; g_cnt2[i] = 0u; }
}

__global__ void cvt_half_kernel(const float* __restrict__ s, __half* __restrict__ d, int n) {
    int i = blockIdx.x * blockDim.x + threadIdx.x;
    if (i < n) d[i] = __float2half(s[i]);
}

// ---------------- fp16 HMMA GEMM (wmma): C[MxN] = A[MxK] @ B[NxK]^T + bias ----------------
#define WG_TM 128
#define WG_TN 64
#define WG_TK 32
#define WG_PAD 8

__global__ __launch_bounds__(256) void hgemm_wmma(
    const __half* __restrict__ A, const __half* __restrict__ Bm,
    const float* __restrict__ bias, float* __restrict__ C,
    int M, int N, int K) {
    __shared__ __half As[WG_TM][WG_TK + WG_PAD];
    __shared__ __half Bs[WG_TN][WG_TK + WG_PAD];
    __shared__ float  Cs[WG_TM][WG_TN];

    const int tid = threadIdx.x;
    const int wid = tid >> 5;
    const int bm = blockIdx.y * WG_TM;
    const int bn = blockIdx.x * WG_TN;
    const int wr = wid >> 1;
    const int wc = wid & 1;

    wmma::fragment<wmma::accumulator, 16, 16, 16, float> acc[2][2];
#pragma unroll
    for (int i = 0; i < 2; i++)
#pragma unroll
        for (int j = 0; j < 2; j++) wmma::fill_fragment(acc[i][j], 0.0f);

    for (int k0 = 0; k0 < K; k0 += WG_TK) {
#pragma unroll
        for (int i = tid; i < WG_TM * WG_TK / 8; i += 256) {
            int r = i >> 2;
            int c = (i & 3) * 8;
            *(uint4*)&As[r][c] = *(const uint4*)(A + (size_t)(bm + r) * K + k0 + c);
        }
#pragma unroll
        for (int i = tid; i < WG_TN * WG_TK / 8; i += 256) {
            int r = i >> 2;
            int c = (i & 3) * 8;
            *(uint4*)&Bs[r][c] = *(const uint4*)(Bm + (size_t)(bn + r) * K + k0 + c);
        }
        __syncthreads();

#pragma unroll
        for (int kk = 0; kk < WG_TK; kk += 16) {
            wmma::fragment<wmma::matrix_a, 16, 16, 16, __half, wmma::row_major> af[2];
            wmma::fragment<wmma::matrix_b, 16, 16, 16, __half, wmma::col_major> bf[2];
#pragma unroll
            for (int i = 0; i < 2; i++)
                wmma::load_matrix_sync(af[i], &As[wr * 32 + i * 16][kk], WG_TK + WG_PAD);
#pragma unroll
            for (int j = 0; j < 2; j++)
                wmma::load_matrix_sync(bf[j], &Bs[wc * 32 + j * 16][kk], WG_TK + WG_PAD);
#pragma unroll
            for (int i = 0; i < 2; i++)
#pragma unroll
                for (int j = 0; j < 2; j++)
                    wmma::mma_sync(acc[i][j], af[i], bf[j], acc[i][j]);
        }
        __syncthreads();
    }

#pragma unroll
    for (int i = 0; i < 2; i++)
#pragma unroll
        for (int j = 0; j < 2; j++)
            wmma::store_matrix_sync(&Cs[wr * 32 + i * 16][wc * 32 + j * 16],
                                    acc[i][j], WG_TN, wmma::mem_row_major);
    __syncthreads();

#pragma unroll
    for (int i = tid; i < WG_TM * WG_TN / 4; i += 256) {
        int r = i >> 4;
        int c = (i & 15) * 4;
        float4 v = *(float4*)&Cs[r][c];
        float4 b4 = *(const float4*)(bias + bn + c);
        v.x += b4.x; v.y += b4.y; v.z += b4.z; v.w += b4.w;
        *(float4*)&C[(size_t)(bm + r) * N + bn + c] = v;
    }
}

// ---------------- persistent recurrence: dual batch-group pipelined barriers ----------------
// 768 threads = 3m x 32ks x 8bq; per group: acc[rp*2+bi] (8 f32x2), 32 k-iters.
// Step: waitA, matmulA, tailA, storeA, arriveA, waitB, matmulB, tailB, storeB, arriveB.
struct RecSmem {
    float W[3][H][HB];             // fp32 weights (96KB)
    u64   red[3][8][8][8];         // warp-reduced partials [m][ksg][bq][j] (12KB)
    __nv_bfloat16 acth[3][HB][GB]; // staged act planes for one group (768B)
    float wb[3][HB];
    float br[HB], bi[HB], tb[HB];
};

// one phase (matmul + reduce + update + store + arrive) for group `grp`
#define REC_PHASE(grp)                                                                   \
    {                                                                                    \
        gbar_wait(grp, t);                                                               \
        const __nv_bfloat16* actp =                                                      \
            g_act + ((size_t)((cur * 2 + (grp)) * 3 + m)) * (H * GB) + bq * 2;           \
        u64 acc[8];                                                                      \
        _Pragma("unroll")                                                                \
        for (int j = 0; j < 8; j++) acc[j] = 0ull;                                       \
        unsigned araw = __ldg((const unsigned*)(actp + ks * GB));                        \
        _Pragma("unroll 4")                                                              \
        for (int i = 0; i < 32; i++) {                                                   \
            int k = ks + (i << 5);                                                       \
            unsigned acur = araw;                                                        \
            if (i < 31) araw = __ldg((const unsigned*)(actp + (k + 32) * GB));           \
            ulonglong2 wA = *(const ulonglong2*)(wk_base + (size_t)k * (HB * 4));        \
            ulonglong2 wB = *(const ulonglong2*)(wk_base + (size_t)k * (HB * 4) + 16);   \
            u64 ad0 = dup2u(bf_lo(acur));                                                \
            u64 ad1 = dup2u(bf_hi(acur));                                                \
            acc[0] = fma2(ad0, wA.x, acc[0]);                                            \
            acc[1] = fma2(ad1, wA.x, acc[1]);                                            \
            acc[2] = fma2(ad0, wA.y, acc[2]);                                            \
            acc[3] = fma2(ad1, wA.y, acc[3]);                                            \
            acc[4] = fma2(ad0, wB.x, acc[4]);                                            \
            acc[5] = fma2(ad1, wB.x, acc[5]);                                            \
            acc[6] = fma2(ad0, wB.y, acc[6]);                                            \
            acc[7] = fma2(ad1, wB.y, acc[7]);                                            \
        }                                                                                \
        _Pragma("unroll")                                                                \
        for (int j = 0; j < 8; j++) {                                                    \
            acc[j] = add2(acc[j], __shfl_xor_sync(0xffffffffu, acc[j], 8));              \
            acc[j] = add2(acc[j], __shfl_xor_sync(0xffffffffu, acc[j], 16));             \
        }                                                                                \
        if ((ks & 3) == 0) {                                                             \
            int ksg = ks >> 2;                                                           \
            _Pragma("unroll")                                                            \
            for (int j = 0; j < 8; j++) sm.red[m][ksg][bq][j] = acc[j];                  \
        }                                                                                \
        __syncthreads();                                                                 \
        if (tid < 256 && (tid >> 7) == (grp)) {                                          \
            int cbL = (tid & 127) >> 3;                                                  \
            int hl  = tid & 7;                                                           \
            int bq2 = cbL >> 1;                                                          \
            int jf  = (hl >> 1) * 4 + (cbL & 1) * 2 + (hl & 1);                          \
            float s0 = 0.0f, s1 = 0.0f, s2 = 0.0f;                                       \
            _Pragma("unroll")                                                            \
            for (int g2 = 0; g2 < 8; g2++) {                                             \
                s0 += ((const float*)&sm.red[0][g2][bq2][0])[jf];                        \
                s1 += ((const float*)&sm.red[1][g2][bq2][0])[jf];                        \
                s2 += ((const float*)&sm.red[2][g2][bq2][0])[jf];                        \
            }                                                                            \
            int bg = (grp)*GB + cbL;                                                     \
            float wr = s0 + sm.wb[0][hl];                                                \
            float wi = s1 + sm.wb[1][hl];                                                \
            float wt = s2 + sm.wb[2][hl];                                                \
            float dr = -zr + wr + ux + sm.br[hl];                                        \
            float di = -zi + wi + ux + sm.bi[hl];                                        \
            float tau = sigmoid_fast(wt) + sm.tb[hl];                                    \
            tau = fminf(fmaxf(tau, 0.01f), 1.0f) + 1e-6f;                                \
            float rtau = __fdividef(1.0f, tau);                                          \
            dr = fminf(fmaxf(dr * rtau, -10.0f), 10.0f);                                 \
            di = fminf(fmaxf(di * rtau, -10.0f), 10.0f);                                 \
            zr = fminf(fmaxf(zr + DT_C * dr, -100.0f), 100.0f);                          \
            zi = fminf(fmaxf(zi + DT_C * di, -100.0f), 100.0f);                          \
            g_ZRh[((long)t * BATCH + bg) * H + hbase + hl] = __float2half(zr);           \
            sm.acth[0][hl][cbL] = __float2bfloat16(tanh_fast(zr));                       \
            sm.acth[1][hl][cbL] = __float2bfloat16(tanh_fast(zi));                       \
            sm.acth[2][hl][cbL] = __float2bfloat16(sqrtf(zr * zr + zi * zi));            \
        }                                                                                \
        __syncthreads();                                                                 \
        if (tid < 48) {                                                                  \
            int p  = tid >> 4;                                                           \
            int of = (tid & 15) * 16;                                                    \
            uint4 v = *(const uint4*)((const char*)&sm.acth[p][0][0] + of);              \
            char* dst = (char*)(g_act + ((size_t)((nxt * 2 + (grp)) * 3 + p) * H          \
                                          + hbase) * GB) + of;                           \
            *(uint4*)dst = v;                                                            \
        }                                                                                \
        __syncthreads();                                                                 \
        gbar_arrive(grp);                                                                \
    }

__global__ void __launch_bounds__(BLOCK_R, 1) rec_kernel(
    const float* __restrict__ Wt_w,
    const float* __restrict__ Wr_b, const float* __restrict__ Wi_b,
    const float* __restrict__ Wt_b, const float* __restrict__ b_real,
    const float* __restrict__ b_imag, const float* __restrict__ tau_bias) {
    extern __shared__ char smem_raw[];
    RecSmem& sm = *reinterpret_cast<RecSmem*>(smem_raw);
    const int tid = threadIdx.x;
    const int hbase = blockIdx.x * HB;

    for (int idx = tid; idx < 3 * HB * H; idx += BLOCK_R) {
        int m   = idx >> 13;
        int rem = idx & 8191;
        int r   = rem >> 10;
        int k   = rem & 1023;
        float w;
        if (m == 0)      w = g_Wr[(long)(hbase + r) * H + k];
        else if (m == 1) w = g_Wi[(long)(hbase + r) * H + k];
        else             w = Wt_w[(long)(hbase + r) * H + k];
        sm.W[m][k][r] = w;
    }
    if (tid < HB) {
        sm.wb[0][tid] = Wr_b[hbase + tid];
        sm.wb[1][tid] = Wi_b[hbase + tid];
        sm.wb[2][tid] = Wt_b[hbase + tid];
        sm.br[tid] = b_real[hbase + tid];
        sm.bi[tid] = b_imag[hbase + tid];
        sm.tb[tid] = tau_bias[hbase + tid];
    }
    __syncthreads();

    const int m  = tid >> 8;          // 0..2
    const int r5 = tid & 255;
    const int ks = r5 >> 3;           // 0..31
    const int bq = r5 & 7;            // 0..7 (2 batches each)
    const char* wk_base = (const char*)&sm.W[m][0][0];

    // state cell: threads 0..255 own (grp = tid>>7, cbL = (tid&127)>>3, hl = tid&7)
    float zr = 0.0f, zi = 0.0f;

    int cur = 0;
    for (int t = 0; t < T_STEPS; t++) {
        const int nxt = cur ^ 1;
        // prefetch Ux for this thread's cell (used in its group's update phase)
        float ux = 0.0f;
        if (tid < 256) {
            int bg = (tid >> 7) * GB + ((tid & 127) >> 3);
            ux = __ldg(&g_Ux[((long)t * BATCH + bg) * H + hbase + (tid & 7)]);
        }

        REC_PHASE(0)
        REC_PHASE(1)

        cur ^= 1;
    }
}

// ---------------- launch ----------------
extern "C" void kernel_launch(void* const* d_in, const int* in_sizes, int n_in,
                              void* d_out, int out_size) {
    const float* x_seq    = (const float*)d_in[0];
    const float* Wr_w     = (const float*)d_in[1];
    const float* Wr_b     = (const float*)d_in[2];
    const float* Wi_w     = (const float*)d_in[3];
    const float* Wi_b     = (const float*)d_in[4];
    const float* U_w      = (const float*)d_in[5];
    const float* U_b      = (const float*)d_in[6];
    const float* Wt_w     = (const float*)d_in[7];
    const float* Wt_b     = (const float*)d_in[8];
    const float* b_real   = (const float*)d_in[9];
    const float* b_imag   = (const float*)d_in[10];
    const float* mask_r   = (const float*)d_in[11];
    const float* mask_i   = (const float*)d_in[12];
    const float* tau_bias = (const float*)d_in[13];
    const float* out_w    = (const float*)d_in[14];
    const float* out_b    = (const float*)d_in[15];
    float* y = (float*)d_out;

    float* p_Ux = nullptr;
    __half *p_xh = nullptr, *p_Uwh = nullptr, *p_owh = nullptr, *p_ZRh = nullptr;
    cudaGetSymbolAddress((void**)&p_Ux, g_Ux);
    cudaGetSymbolAddress((void**)&p_xh, g_xh);
    cudaGetSymbolAddress((void**)&p_Uwh, g_Uwh);
    cudaGetSymbolAddress((void**)&p_owh, g_owh);
    cudaGetSymbolAddress((void**)&p_ZRh, g_ZRh);

    prep_kernel<<<(H * H + 255) / 256, 256>>>(Wr_w, mask_r, Wi_w, mask_i);
    init_kernel<<<(2 * 2 * 3 * H * GB + 255) / 256, 256>>>();

    cvt_half_kernel<<<(T_STEPS * BATCH * DIN + 255) / 256, 256>>>(x_seq, p_xh, T_STEPS * BATCH * DIN);
    cvt_half_kernel<<<(H * DIN + 255) / 256, 256>>>(U_w, p_Uwh, H * DIN);
    cvt_half_kernel<<<(H * H + 255) / 256, 256>>>(out_w, p_owh, H * H);

    // Ux = x @ U_w^T + U_b  (HMMA)
    {
        dim3 grid(H / WG_TN, (T_STEPS * BATCH) / WG_TM);
        hgemm_wmma<<<grid, 256>>>(p_xh, p_Uwh, U_b, p_Ux, T_STEPS * BATCH, H, DIN);
    }

    // persistent recurrence (dual-group pipelined barriers)
    {
        int smem = (int)sizeof(RecSmem);
        cudaFuncSetAttribute(rec_kernel, cudaFuncAttributeMaxDynamicSharedMemorySize, smem);
        rec_kernel<<<GRID_R, BLOCK_R, smem>>>(Wt_w, Wr_b, Wi_b, Wt_b, b_real, b_imag, tau_bias);
    }

    // y = ZR @ out_w^T + out_b  (HMMA)
    {
        dim3 grid(H / WG_TN, (T_STEPS * BATCH) / WG_TM);
        hgemm_wmma<<<grid, 256>>>(p_ZRh, p_owh, out_b, y, T_STEPS * BATCH, H, H);
    }
}